// round 16
// baseline (speedup 1.0000x reference)
#include <cuda_runtime.h>
#include <cuda_bf16.h>
#include <math.h>
#include <stdint.h>

#define HH 160
#define WW 160
#define HWW (160*160)
#define BB 4

typedef unsigned long long u64;

// ======================= PTX helpers (base ISA only) ========================
__device__ __forceinline__ uint32_t smem_u32(const void* p){
    uint32_t a; asm("{ .reg .u64 t; cvta.to.shared.u64 t, %1; cvt.u32.u64 %0, t; }" : "=r"(a) : "l"(p));
    return a;
}
__device__ __forceinline__ void cp16(uint32_t dst, const void* src){
    asm volatile("cp.async.ca.shared.global [%0], [%1], 16;" :: "r"(dst), "l"(src) : "memory");
}
__device__ __forceinline__ void cp16z(uint32_t dst, const void* src, int sz){
    asm volatile("cp.async.ca.shared.global [%0], [%1], 16, %2;" :: "r"(dst), "l"(src), "r"(sz) : "memory");
}
#define CP_COMMIT() asm volatile("cp.async.commit_group;" ::: "memory")

__device__ __forceinline__ void ldsm4(uint32_t* r, uint32_t a){
    asm volatile("ldmatrix.sync.aligned.m8n8.x4.shared.b16 {%0,%1,%2,%3}, [%4];"
      : "=r"(r[0]),"=r"(r[1]),"=r"(r[2]),"=r"(r[3]) : "r"(a));
}
__device__ __forceinline__ void mma_bf16(float* d, const uint32_t* a, const uint32_t* b){
    asm volatile("mma.sync.aligned.m16n8k16.row.col.f32.bf16.bf16.f32 "
      "{%0,%1,%2,%3}, {%4,%5,%6,%7}, {%8,%9}, {%0,%1,%2,%3};"
      : "+f"(d[0]),"+f"(d[1]),"+f"(d[2]),"+f"(d[3])
      : "r"(a[0]),"r"(a[1]),"r"(a[2]),"r"(a[3]),"r"(b[0]),"r"(b[1]));
}
__device__ __forceinline__ uint32_t swz(uint32_t r){ return r ^ ((r>>3)&0x70); }

// ================= device-global scratch (no allocation allowed) ============
__device__ __align__(16) float g_off1[BB*64*HWW];        // conv1 out NCHW (residual)
__device__ __align__(16) float g_off[BB*18*HWW];         // offsets NCHW
__device__ __align__(16) float g_xt [BB*HWW*64];         // in_aux NHWC fp32 (deform)
__device__ __align__(16) __nv_bfloat16 g_xh[BB*HWW*64];  // conv1 out NHWC bf16 hi
__device__ __align__(16) __nv_bfloat16 g_xl[BB*HWW*64];  // conv1 out NHWC bf16 lo
__device__ __align__(16) __nv_bfloat16 g_rh[(size_t)BB*HWW*192]; // concat NHWC hi
__device__ __align__(16) __nv_bfloat16 g_rl[(size_t)BB*HWW*192]; // concat NHWC lo
__device__ __align__(16) __nv_bfloat16 g_wb  [2*3*9*64*64]; // ASPP W [split][br][tap][co][ci]
__device__ __align__(16) __nv_bfloat16 g_arwb[2*3*64*64];   // fuse W [split][sub][co][ci]
__device__ __align__(16) __nv_bfloat16 g_dwb [2*9*64*64];   // deform W [split][tap][co][ci]
__device__ __align__(16) __nv_bfloat16 g_w01b[2*2*64*64];   // conv1 W [split][half][co][ci]
__device__ float g_w02t[64*18];

// ---------------------------------------------------------------------------
// prep: weight transposes + bf16 splits
// ---------------------------------------------------------------------------
__global__ void k_prep(const float* __restrict__ w01, const float* __restrict__ a1w,
                       const float* __restrict__ a2w, const float* __restrict__ a3w,
                       const float* __restrict__ arw, const float* __restrict__ w02,
                       const float* __restrict__ dw)
{
    int i = blockIdx.x*256 + threadIdx.x;
    if (i < 1152) { int c = i/18, j = i - c*18; g_w02t[i] = w02[j*64 + c]; return; }
    i -= 1152;
    if (i < 221184) {
        int s  = i / 110592;
        int q  = i % 110592;
        int br = q / 36864;
        int q2 = q % 36864;
        int tap = q2 / 4096;
        int r   = q2 % 4096;
        int co = r >> 6, ci = r & 63;
        const float* w = (br==0)?a1w:(br==1)?a2w:a3w;
        float v = w[(co*64+ci)*9 + tap];
        __nv_bfloat16 h = __float2bfloat16(v);
        g_wb[i] = (s==0) ? h : __float2bfloat16(v - __bfloat162float(h));
        return;
    }
    i -= 221184;
    if (i < 24576) {
        int s = i / 12288, q = i % 12288;
        int sub = q / 4096, r = q % 4096;
        int co = r >> 6, ci = r & 63;
        float v = arw[co*192 + sub*64 + ci];
        __nv_bfloat16 h = __float2bfloat16(v);
        g_arwb[i] = (s==0) ? h : __float2bfloat16(v - __bfloat162float(h));
        return;
    }
    i -= 24576;
    if (i < 73728) {
        int s = i / 36864, q = i % 36864;
        int tap = q / 4096, r = q % 4096;
        int co = r >> 6, ci = r & 63;
        float v = dw[(co*64+ci)*9 + tap];
        __nv_bfloat16 h = __float2bfloat16(v);
        g_dwb[i] = (s==0) ? h : __float2bfloat16(v - __bfloat162float(h));
        return;
    }
    i -= 73728;
    if (i < 16384) {
        int s = i / 8192, q = i % 8192;
        int half = q / 4096, r = q % 4096;
        int co = r >> 6, ci = r & 63;
        float v = w01[co*128 + half*64 + ci];
        __nv_bfloat16 h = __float2bfloat16(v);
        g_w01b[i] = (s==0) ? h : __float2bfloat16(v - __bfloat162float(h));
    }
}

// ---------------------------------------------------------------------------
// Kernel 1: conv1 1x1 128->64 + LReLU via mma, loading NCHW fp32 directly.
// half=0 staging pass ALSO writes g_xt (in_aux NHWC fp32).
// ---------------------------------------------------------------------------
#define C1_SMEM 100352

__global__ __launch_bounds__(256,2) void k_conv1_mma(
    const float* __restrict__ aux, const float* __restrict__ refi,
    const float* __restrict__ b01)
{
    extern __shared__ char smem[];
    uint32_t sb = smem_u32(smem);
    float* ts = (float*)(smem + 65536);     // [64][133] fp32 staging
    int tid = threadIdx.x, lane = tid&31, wid = tid>>5;
    int pxb = blockIdx.x*128;
    int b = pxb/HWW, hw0 = pxb%HWW;

    #pragma unroll
    for (int half = 0; half < 2; half++) {
        const float* src = (half ? refi : aux) + (size_t)b*64*HWW + hw0;
        if (half) __syncthreads();
        for (int i = tid; i < 2048; i += 256) {
            int ci = i>>5, g = i&31;
            float4 v = *(const float4*)(src + (size_t)ci*HWW + g*4);
            float* tp = &ts[ci*133 + g*4];
            tp[0]=v.x; tp[1]=v.y; tp[2]=v.z; tp[3]=v.w;
        }
        __syncthreads();
        for (int c = tid; c < 1024; c += 256) {
            int p = c>>3, ci8 = c&7;
            uint32_t hp[4], lp[4];
            #pragma unroll
            for (int k2 = 0; k2 < 4; k2++) {
                float v0 = ts[(ci8*8 + 2*k2  )*133 + p];
                float v1 = ts[(ci8*8 + 2*k2+1)*133 + p];
                __nv_bfloat16 h0 = __float2bfloat16(v0);
                __nv_bfloat16 h1 = __float2bfloat16(v1);
                hp[k2] = ((uint32_t)__bfloat16_as_ushort(h1)<<16) | __bfloat16_as_ushort(h0);
                __nv_bfloat162 l2 = __floats2bfloat162_rn(v0 - __bfloat162float(h0),
                                                          v1 - __bfloat162float(h1));
                lp[k2] = *(uint32_t*)&l2;
            }
            uint32_t rel = swz((uint32_t)(p*128 + ci8*16));
            *(uint4*)(smem + (half*2+0)*16384 + rel) = make_uint4(hp[0],hp[1],hp[2],hp[3]);
            *(uint4*)(smem + (half*2+1)*16384 + rel) = make_uint4(lp[0],lp[1],lp[2],lp[3]);
        }
        if (half == 0) {
            float* op = g_xt + ((size_t)b*HWW + hw0)*64;
            for (int i = tid; i < 8192; i += 256) {
                int p = i>>6, c = i&63;
                op[p*64 + c] = ts[c*133 + p];
            }
        }
    }
    __syncthreads();

    for (int c = tid; c < 2048; c += 256) {
        int t = c>>9, r = c&511;
        int half = t>>1, split = t&1;
        int co = r>>3, ci8 = r&7;
        const __nv_bfloat16* src = g_w01b + ((size_t)(split*2+half)*4096 + co*64 + ci8*8);
        cp16(sb + 65536 + t*8192 + swz((uint32_t)(co*128 + ci8*16)), src);
    }
    CP_COMMIT();
    asm volatile("cp.async.wait_group 0;" ::: "memory");
    __syncthreads();

    int m0 = (wid>>1)*32, n0 = (wid&1)*32;
    float d[2][4][4];
    #pragma unroll
    for (int mt = 0; mt < 2; mt++)
        #pragma unroll
        for (int nt = 0; nt < 4; nt++)
            #pragma unroll
            for (int e = 0; e < 4; e++) d[mt][nt][e] = 0.f;

    #pragma unroll
    for (int half = 0; half < 2; half++) {
        uint32_t Ah = sb + (half*2+0)*16384;
        uint32_t Al = sb + (half*2+1)*16384;
        uint32_t Bh = sb + 65536 + (uint32_t)((half*2+0)*8192);
        uint32_t Bl = sb + 65536 + (uint32_t)((half*2+1)*8192);
        #pragma unroll
        for (int ks = 0; ks < 4; ks++) {
            uint32_t ah[2][4], al[2][4], bh[4][2], bl[4][2];
            #pragma unroll
            for (int mt = 0; mt < 2; mt++) {
                uint32_t rel = (uint32_t)((m0 + mt*16 + (lane&15))*128
                                          + ks*32 + (lane>>4)*16);
                ldsm4(ah[mt], Ah + swz(rel));
                ldsm4(al[mt], Al + swz(rel));
            }
            #pragma unroll
            for (int nt2 = 0; nt2 < 2; nt2++) {
                int mid = lane>>3;
                int row = n0 + nt2*16 + (mid>>1)*8 + (lane&7);
                uint32_t rel = (uint32_t)(row*128 + ks*32 + (mid&1)*16);
                uint32_t r4[4];
                ldsm4(r4, Bh + swz(rel));
                bh[nt2*2][0]=r4[0]; bh[nt2*2][1]=r4[1];
                bh[nt2*2+1][0]=r4[2]; bh[nt2*2+1][1]=r4[3];
                ldsm4(r4, Bl + swz(rel));
                bl[nt2*2][0]=r4[0]; bl[nt2*2][1]=r4[1];
                bl[nt2*2+1][0]=r4[2]; bl[nt2*2+1][1]=r4[3];
            }
            #pragma unroll
            for (int mt = 0; mt < 2; mt++)
                #pragma unroll
                for (int nt = 0; nt < 4; nt++) {
                    mma_bf16(d[mt][nt], ah[mt], bh[nt]);
                    mma_bf16(d[mt][nt], ah[mt], bl[nt]);
                    mma_bf16(d[mt][nt], al[mt], bh[nt]);
                }
        }
    }

    float* ep = (float*)smem;
    __syncthreads();
    #pragma unroll
    for (int mt = 0; mt < 2; mt++)
        #pragma unroll
        for (int nt = 0; nt < 4; nt++) {
            int px = m0 + mt*16 + (lane>>2);
            int co = n0 + nt*8 + (lane&3)*2;
            ep[px*66 + co]       = d[mt][nt][0];
            ep[px*66 + co + 1]   = d[mt][nt][1];
            ep[(px+8)*66 + co]   = d[mt][nt][2];
            ep[(px+8)*66 + co+1] = d[mt][nt][3];
        }
    __syncthreads();
    float* op = g_off1 + (size_t)b*64*HWW + hw0;
    for (int i = tid; i < 8192; i += 256) {
        int co = i>>7, p = i&127;
        float v = ep[p*66 + co] + __ldg(&b01[co]);
        v = (v >= 0.f) ? v : 0.1f*v;
        op[(size_t)co*HWW + p] = v;
    }
    for (int i = tid; i < 8192; i += 256) {
        int p = i>>6, co = i&63;
        float v = ep[p*66 + co] + __ldg(&b01[co]);
        v = (v >= 0.f) ? v : 0.1f*v;
        size_t gp = (size_t)b*HWW + hw0 + p;
        __nv_bfloat16 h = __float2bfloat16(v);
        g_xh[gp*64 + co] = h;
        g_xl[gp*64 + co] = __float2bfloat16(v - __bfloat162float(h));
    }
}

// ---------------------------------------------------------------------------
// Kernel 2: ASPP dilated 3x3 via mma.sync bf16-split (96KB, 2 CTAs/SM)
// ---------------------------------------------------------------------------
#define ASPP_SMEM 98304

__global__ __launch_bounds__(256,2) void k_aspp_mma(
    const float* __restrict__ b1, const float* __restrict__ b2,
    const float* __restrict__ b3)
{
    extern __shared__ char smem[];
    uint32_t sb = smem_u32(smem);
    int tid = threadIdx.x, lane = tid&31, wid = tid>>5;
    int z = blockIdx.z, b = z&3, br = z>>2;
    int D = 1<<br;
    const float* bias = (br==0)?b1:((br==1)?b2:b3);
    int x0 = blockIdx.x*16, y0 = blockIdx.y*8;

    auto issueT = [&](int t, int stage){
        int ky = t/3, kx = t - ky*3;
        int dy = (ky-1)*D, dx = (kx-1)*D;
        #pragma unroll
        for (int j = 0; j < 8; j++) {
            int c = tid + j*256;
            int split = c>>10, rem = c&1023, p = rem>>3, ci8 = rem&7;
            int gy = y0 + (p>>4) + dy, gx = x0 + (p&15) + dx;
            bool ok = (gy>=0)&&(gy<HH)&&(gx>=0)&&(gx<WW);
            const __nv_bfloat16* base = split ? g_xl : g_xh;
            const __nv_bfloat16* src =
                base + (((size_t)b*HWW + (ok ? gy*WW+gx : 0))*64 + ci8*8);
            uint32_t rel = (uint32_t)(p*128 + ci8*16);
            cp16z(sb + (stage*2+split)*16384 + swz(rel), src, ok?16:0);
        }
        #pragma unroll
        for (int j = 0; j < 4; j++) {
            int c = tid + j*256;
            int split = c>>9, r = c&511;
            int co = r>>3, ci8 = r&7;
            const __nv_bfloat16* src =
                g_wb + (((size_t)(split*3+br)*9 + t)*4096 + co*64 + ci8*8);
            cp16(sb + 65536 + (stage*2+split)*8192 + swz((uint32_t)(co*128 + ci8*16)), src);
        }
        CP_COMMIT();
    };
    issueT(0, 0);
    issueT(1, 1);

    int m0 = (wid>>1)*32, n0 = (wid&1)*32;
    float d[2][4][4];
    #pragma unroll
    for (int mt = 0; mt < 2; mt++)
        #pragma unroll
        for (int nt = 0; nt < 4; nt++)
            #pragma unroll
            for (int e = 0; e < 4; e++) d[mt][nt][e] = 0.f;

    #pragma unroll 1
    for (int t = 0; t < 9; t++) {
        if (t < 8) asm volatile("cp.async.wait_group 1;" ::: "memory");
        else       asm volatile("cp.async.wait_group 0;" ::: "memory");
        __syncthreads();
        int stage = t & 1;
        uint32_t Ah = sb + (stage*2+0)*16384;
        uint32_t Al = sb + (stage*2+1)*16384;
        uint32_t Bh = sb + 65536 + (uint32_t)((stage*2+0)*8192);
        uint32_t Bl = sb + 65536 + (uint32_t)((stage*2+1)*8192);
        #pragma unroll
        for (int ks = 0; ks < 4; ks++) {
            uint32_t ah[2][4], al[2][4], bh[4][2], bl[4][2];
            #pragma unroll
            for (int mt = 0; mt < 2; mt++) {
                uint32_t rel = (uint32_t)((m0 + mt*16 + (lane&15))*128
                                          + ks*32 + (lane>>4)*16);
                ldsm4(ah[mt], Ah + swz(rel));
                ldsm4(al[mt], Al + swz(rel));
            }
            #pragma unroll
            for (int nt2 = 0; nt2 < 2; nt2++) {
                int mid = lane>>3;
                int row = n0 + nt2*16 + (mid>>1)*8 + (lane&7);
                uint32_t rel = (uint32_t)(row*128 + ks*32 + (mid&1)*16);
                uint32_t r4[4];
                ldsm4(r4, Bh + swz(rel));
                bh[nt2*2][0]=r4[0]; bh[nt2*2][1]=r4[1];
                bh[nt2*2+1][0]=r4[2]; bh[nt2*2+1][1]=r4[3];
                ldsm4(r4, Bl + swz(rel));
                bl[nt2*2][0]=r4[0]; bl[nt2*2][1]=r4[1];
                bl[nt2*2+1][0]=r4[2]; bl[nt2*2+1][1]=r4[3];
            }
            #pragma unroll
            for (int mt = 0; mt < 2; mt++)
                #pragma unroll
                for (int nt = 0; nt < 4; nt++) {
                    mma_bf16(d[mt][nt], ah[mt], bh[nt]);
                    mma_bf16(d[mt][nt], ah[mt], bl[nt]);
                    mma_bf16(d[mt][nt], al[mt], bh[nt]);
                }
        }
        __syncthreads();
        if (t < 7) issueT(t+2, stage);
    }

    float* ep = (float*)smem;
    #pragma unroll
    for (int mt = 0; mt < 2; mt++)
        #pragma unroll
        for (int nt = 0; nt < 4; nt++) {
            int px = m0 + mt*16 + (lane>>2);
            int co = n0 + nt*8 + (lane&3)*2;
            ep[px*66 + co]       = d[mt][nt][0];
            ep[px*66 + co + 1]   = d[mt][nt][1];
            ep[(px+8)*66 + co]   = d[mt][nt][2];
            ep[(px+8)*66 + co+1] = d[mt][nt][3];
        }
    __syncthreads();
    for (int i = tid; i < 8192; i += 256) {
        int p = i>>6, co = i&63;
        float v = ep[p*66 + co] + __ldg(&bias[co]);
        v = (v >= 0.f) ? v : 0.1f*v;
        size_t gp = (size_t)b*HWW + (size_t)(y0 + (p>>4))*WW + x0 + (p&15);
        __nv_bfloat16 h = __float2bfloat16(v);
        g_rh[gp*192 + br*64 + co] = h;
        g_rl[gp*192 + br*64 + co] = __float2bfloat16(v - __bfloat162float(h));
    }
}

// ---------------------------------------------------------------------------
// Kernel 3: fuse 1x1 192->64 + bias + residual + fused offset head (64->18).
// Head epilogue re-parallelized: thread=(px, jg), 9 independent accumulators,
// w2 reads are warp-uniform broadcasts.
// ---------------------------------------------------------------------------
#define FUSE_SMEM 114688

__global__ __launch_bounds__(256,2) void k_fuse_mma(const float* __restrict__ arb,
                                                    const float* __restrict__ b02)
{
    extern __shared__ char smem[];
    uint32_t sb = smem_u32(smem);
    int tid = threadIdx.x, lane = tid&31, wid = tid>>5;
    int pxb = blockIdx.x*128;
    int b = pxb/HWW, hw0 = pxb%HWW;

    auto issueA = [&](int sub, int stage){
        #pragma unroll
        for (int j = 0; j < 8; j++) {
            int c = tid + j*256;
            int split = c>>10, r = c&1023;
            int p = r>>3, ci8 = r&7;
            const __nv_bfloat16* base = split ? g_rl : g_rh;
            const __nv_bfloat16* src = base + ((size_t)(b*HWW + hw0 + p)*192 + sub*64 + ci8*8);
            cp16(sb + (stage*2+split)*16384 + swz((uint32_t)(p*128 + ci8*16)), src);
        }
        CP_COMMIT();
    };
    for (int c = tid; c < 3072; c += 256) {
        int t = c>>9, r = c&511;
        int sub = t>>1, split = t&1;
        int co = r>>3, ci8 = r&7;
        const __nv_bfloat16* src = g_arwb + ((size_t)(split*3+sub)*4096 + co*64 + ci8*8);
        cp16(sb + 65536 + t*8192 + swz((uint32_t)(co*128 + ci8*16)), src);
    }
    issueA(0, 0);
    issueA(1, 1);

    int m0 = (wid>>1)*32, n0 = (wid&1)*32;
    float d[2][4][4];
    #pragma unroll
    for (int mt = 0; mt < 2; mt++)
        #pragma unroll
        for (int nt = 0; nt < 4; nt++)
            #pragma unroll
            for (int e = 0; e < 4; e++) d[mt][nt][e] = 0.f;

    #pragma unroll 1
    for (int sub = 0; sub < 3; sub++) {
        if (sub < 2) asm volatile("cp.async.wait_group 1;" ::: "memory");
        else         asm volatile("cp.async.wait_group 0;" ::: "memory");
        __syncthreads();
        int stage = sub & 1;
        uint32_t Ah = sb + (stage*2+0)*16384;
        uint32_t Al = sb + (stage*2+1)*16384;
        uint32_t Bh = sb + 65536 + (uint32_t)((sub*2+0)*8192);
        uint32_t Bl = sb + 65536 + (uint32_t)((sub*2+1)*8192);
        #pragma unroll
        for (int ks = 0; ks < 4; ks++) {
            uint32_t ah[2][4], al[2][4], bh[4][2], bl[4][2];
            #pragma unroll
            for (int mt = 0; mt < 2; mt++) {
                uint32_t rel = (uint32_t)((m0 + mt*16 + (lane&15))*128
                                          + ks*32 + (lane>>4)*16);
                ldsm4(ah[mt], Ah + swz(rel));
                ldsm4(al[mt], Al + swz(rel));
            }
            #pragma unroll
            for (int nt2 = 0; nt2 < 2; nt2++) {
                int mid = lane>>3;
                int row = n0 + nt2*16 + (mid>>1)*8 + (lane&7);
                uint32_t rel = (uint32_t)(row*128 + ks*32 + (mid&1)*16);
                uint32_t r4[4];
                ldsm4(r4, Bh + swz(rel));
                bh[nt2*2][0]=r4[0]; bh[nt2*2][1]=r4[1];
                bh[nt2*2+1][0]=r4[2]; bh[nt2*2+1][1]=r4[3];
                ldsm4(r4, Bl + swz(rel));
                bl[nt2*2][0]=r4[0]; bl[nt2*2][1]=r4[1];
                bl[nt2*2+1][0]=r4[2]; bl[nt2*2+1][1]=r4[3];
            }
            #pragma unroll
            for (int mt = 0; mt < 2; mt++)
                #pragma unroll
                for (int nt = 0; nt < 4; nt++) {
                    mma_bf16(d[mt][nt], ah[mt], bh[nt]);
                    mma_bf16(d[mt][nt], ah[mt], bl[nt]);
                    mma_bf16(d[mt][nt], al[mt], bh[nt]);
                }
        }
        __syncthreads();
        if (sub < 1) issueA(sub+2, stage);
    }

    float* ep = (float*)smem;              // [128][66]
    float* w2 = (float*)(smem + 36864);    // [64][18]
    #pragma unroll
    for (int mt = 0; mt < 2; mt++)
        #pragma unroll
        for (int nt = 0; nt < 4; nt++) {
            int px = m0 + mt*16 + (lane>>2);
            int co = n0 + nt*8 + (lane&3)*2;
            ep[px*66 + co]       = d[mt][nt][0];
            ep[px*66 + co + 1]   = d[mt][nt][1];
            ep[(px+8)*66 + co]   = d[mt][nt][2];
            ep[(px+8)*66 + co+1] = d[mt][nt][3];
        }
    for (int i = tid; i < 1152; i += 256) w2[i] = g_w02t[i];
    __syncthreads();

    const float* xb = g_off1 + (size_t)b*64*HWW + hw0;
    for (int i = tid; i < 8192; i += 256) {
        int co = i>>7, p = i&127;
        ep[p*66 + co] += __ldg(&arb[co]) + xb[(size_t)co*HWW + p];
    }
    __syncthreads();

    // head: thread = (px, jg); 9 accumulators; w2 reads warp-uniform
    {
        int px = tid & 127, jg = tid >> 7;      // jg: 0 -> j 0..8, 1 -> j 9..17
        float acc[9];
        #pragma unroll
        for (int t = 0; t < 9; t++) acc[t] = __ldg(&b02[jg*9 + t]);
        const float* er = &ep[px*66];
        for (int co = 0; co < 64; co++) {
            float e = er[co];
            const float* wr = &w2[co*18 + jg*9];
            #pragma unroll
            for (int t = 0; t < 9; t++) acc[t] += e * wr[t];
        }
        float* oo = g_off + (size_t)b*18*HWW + hw0 + px;
        #pragma unroll
        for (int t = 0; t < 9; t++) oo[(size_t)(jg*9 + t)*HWW] = acc[t];
    }
}

// ---------------------------------------------------------------------------
// Kernel 4: deformable conv via mma.sync bf16-split (2 CTAs/SM).
// All 9 taps' bilinear params precomputed once (full CTA), 2 syncs/tap.
// smem: samp 0..32K, W 32..64K, pw 65536 (18432B), pi 83968 (18432B).
// ---------------------------------------------------------------------------
#define DEF_SMEM 102400

__global__ __launch_bounds__(256,2) void k_deform_mma(const float* __restrict__ db,
                                                      float* __restrict__ out)
{
    extern __shared__ char smem[];
    uint32_t sb = smem_u32(smem);
    int tid = threadIdx.x, lane = tid&31, wid = tid>>5;
    int pxb = blockIdx.x*128;
    int b = pxb/HWW, hw0 = pxb%HWW;
    float* pw_s = (float*)(smem + 65536);   // [9][128][4]
    int*   pi_s = (int*)(smem + 83968);     // [9][128][4]

    auto issueW = [&](int t){
        int s = t&1;
        #pragma unroll
        for (int j = 0; j < 4; j++) {
            int c = tid + j*256;
            int split = c>>9, r = c&511;
            int co = r>>3, ci8 = r&7;
            const __nv_bfloat16* src = g_dwb + ((size_t)(split*9 + t)*4096 + co*64 + ci8*8);
            cp16(sb + 32768 + s*16384 + split*8192 + swz((uint32_t)(co*128 + ci8*16)), src);
        }
        CP_COMMIT();
    };
    issueW(0);

    // ---- precompute all 9 taps' bilinear params (1152 slots) ----
    for (int i = tid; i < 1152; i += 256) {
        int k = i >> 7, px = i & 127;
        int hw = hw0 + px;
        int h = hw/WW, w = hw - h*WW;
        int ky = k/3, kx = k - ky*3;
        const float* offb = g_off + (size_t)b*18*HWW + hw;
        float py  = (float)(h - 1 + ky) + offb[(size_t)(2*k)*HWW];
        float pxf = (float)(w - 1 + kx) + offb[(size_t)(2*k+1)*HWW];
        float fy = floorf(py), fx = floorf(pxf);
        int iy = (int)fy, ix = (int)fx;
        float wy = py - fy, wx = pxf - fx;
        bool vy0 = (iy   >= 0 && iy   < HH);
        bool vy1 = (iy+1 >= 0 && iy+1 < HH);
        bool vx0 = (ix   >= 0 && ix   < WW);
        bool vx1 = (ix+1 >= 0 && ix+1 < WW);
        float w00 = (1.f-wy)*(1.f-wx); if (!(vy0&&vx0)) w00 = 0.f;
        float w01 = (1.f-wy)*wx;       if (!(vy0&&vx1)) w01 = 0.f;
        float w10 = wy*(1.f-wx);       if (!(vy1&&vx0)) w10 = 0.f;
        float w11 = wy*wx;             if (!(vy1&&vx1)) w11 = 0.f;
        int cy0 = min(max(iy,0),HH-1),   cy1 = min(max(iy+1,0),HH-1);
        int cx0 = min(max(ix,0),WW-1),   cx1 = min(max(ix+1,0),WW-1);
        int base = (k*128 + px)*4;
        pw_s[base+0] = w00; pw_s[base+1] = w01;
        pw_s[base+2] = w10; pw_s[base+3] = w11;
        pi_s[base+0] = (cy0*WW + cx0)*64; pi_s[base+1] = (cy0*WW + cx1)*64;
        pi_s[base+2] = (cy1*WW + cx0)*64; pi_s[base+3] = (cy1*WW + cx1)*64;
    }
    __syncthreads();

    int m0 = (wid>>1)*32, n0 = (wid&1)*32;
    float d[2][4][4];
    #pragma unroll
    for (int mt = 0; mt < 2; mt++)
        #pragma unroll
        for (int nt = 0; nt < 4; nt++)
            #pragma unroll
            for (int e = 0; e < 4; e++) d[mt][nt][e] = 0.f;

    const float* xb = g_xt + (size_t)b*HWW*64;

    #pragma unroll 1
    for (int k = 0; k < 9; k++) {
        if (k < 8) issueW(k+1);
        // sample + split to bf16 hi/lo smem tiles
        {
            int px = tid>>1, ch0 = (tid&1)*32;
            int base = (k*128 + px)*4;
            float w00 = pw_s[base+0], w01v = pw_s[base+1];
            float w10 = pw_s[base+2], w11  = pw_s[base+3];
            int i00 = pi_s[base+0], i01 = pi_s[base+1];
            int i10 = pi_s[base+2], i11 = pi_s[base+3];
            #pragma unroll
            for (int q = 0; q < 8; q++) {
                int c = ch0 + q*4;
                float4 A = *(const float4*)(xb + i00 + c);
                float4 Bq= *(const float4*)(xb + i01 + c);
                float4 C = *(const float4*)(xb + i10 + c);
                float4 Dq= *(const float4*)(xb + i11 + c);
                float s0 = w00*A.x + w01v*Bq.x + w10*C.x + w11*Dq.x;
                float s1 = w00*A.y + w01v*Bq.y + w10*C.y + w11*Dq.y;
                float s2 = w00*A.z + w01v*Bq.z + w10*C.z + w11*Dq.z;
                float s3 = w00*A.w + w01v*Bq.w + w10*C.w + w11*Dq.w;
                __nv_bfloat16 h0 = __float2bfloat16(s0);
                __nv_bfloat16 h1 = __float2bfloat16(s1);
                __nv_bfloat16 h2 = __float2bfloat16(s2);
                __nv_bfloat16 h3 = __float2bfloat16(s3);
                uint32_t hp0 = (uint32_t)__bfloat16_as_ushort(h1)<<16 | __bfloat16_as_ushort(h0);
                uint32_t hp1 = (uint32_t)__bfloat16_as_ushort(h3)<<16 | __bfloat16_as_ushort(h2);
                __nv_bfloat162 lp0 = __floats2bfloat162_rn(s0 - __bfloat162float(h0),
                                                           s1 - __bfloat162float(h1));
                __nv_bfloat162 lp1 = __floats2bfloat162_rn(s2 - __bfloat162float(h2),
                                                           s3 - __bfloat162float(h3));
                uint32_t rel = (uint32_t)(px*128 + c*2);
                *(uint32_t*)(smem + swz(rel))          = hp0;
                *(uint32_t*)(smem + swz(rel+4))        = hp1;
                *(uint32_t*)(smem + 16384 + swz(rel))  = *(uint32_t*)&lp0;
                *(uint32_t*)(smem + 16384 + swz(rel+4))= *(uint32_t*)&lp1;
            }
        }
        if (k < 8) asm volatile("cp.async.wait_group 1;" ::: "memory");
        else       asm volatile("cp.async.wait_group 0;" ::: "memory");
        __syncthreads();

        uint32_t Ah = sb, Al = sb + 16384;
        uint32_t Bh = sb + 32768 + (uint32_t)((k&1)*16384);
        uint32_t Bl = Bh + 8192;
        #pragma unroll
        for (int ks = 0; ks < 4; ks++) {
            uint32_t ah[2][4], al[2][4], bh[4][2], bl[4][2];
            #pragma unroll
            for (int mt = 0; mt < 2; mt++) {
                uint32_t rel = (uint32_t)((m0 + mt*16 + (lane&15))*128
                                          + ks*32 + (lane>>4)*16);
                ldsm4(ah[mt], Ah + swz(rel));
                ldsm4(al[mt], Al + swz(rel));
            }
            #pragma unroll
            for (int nt2 = 0; nt2 < 2; nt2++) {
                int mid = lane>>3;
                int row = n0 + nt2*16 + (mid>>1)*8 + (lane&7);
                uint32_t rel = (uint32_t)(row*128 + ks*32 + (mid&1)*16);
                uint32_t r4[4];
                ldsm4(r4, Bh + swz(rel));
                bh[nt2*2][0]=r4[0]; bh[nt2*2][1]=r4[1];
                bh[nt2*2+1][0]=r4[2]; bh[nt2*2+1][1]=r4[3];
                ldsm4(r4, Bl + swz(rel));
                bl[nt2*2][0]=r4[0]; bl[nt2*2][1]=r4[1];
                bl[nt2*2+1][0]=r4[2]; bl[nt2*2+1][1]=r4[3];
            }
            #pragma unroll
            for (int mt = 0; mt < 2; mt++)
                #pragma unroll
                for (int nt = 0; nt < 4; nt++) {
                    mma_bf16(d[mt][nt], ah[mt], bh[nt]);
                    mma_bf16(d[mt][nt], ah[mt], bl[nt]);
                    mma_bf16(d[mt][nt], al[mt], bh[nt]);
                }
        }
        __syncthreads();
    }

    float* ep = (float*)smem;
    #pragma unroll
    for (int mt = 0; mt < 2; mt++)
        #pragma unroll
        for (int nt = 0; nt < 4; nt++) {
            int px = m0 + mt*16 + (lane>>2);
            int co = n0 + nt*8 + (lane&3)*2;
            ep[px*66 + co]       = d[mt][nt][0];
            ep[px*66 + co + 1]   = d[mt][nt][1];
            ep[(px+8)*66 + co]   = d[mt][nt][2];
            ep[(px+8)*66 + co+1] = d[mt][nt][3];
        }
    __syncthreads();
    float* op = out + (size_t)b*64*HWW + hw0;
    for (int i = tid; i < 8192; i += 256) {
        int co = i>>7, p = i&127;
        op[(size_t)co*HWW + p] = ep[p*66 + co] + __ldg(&db[co]);
    }
}

// ===========================================================================
extern "C" void kernel_launch(void* const* d_in, const int* in_sizes, int n_in,
                              void* d_out, int out_size)
{
    const float* in_aux = (const float*)d_in[0];
    const float* in_ref = (const float*)d_in[1];
    const float* w01    = (const float*)d_in[2];
    const float* b01    = (const float*)d_in[3];
    const float* a1w    = (const float*)d_in[4];
    const float* a1b    = (const float*)d_in[5];
    const float* a2w    = (const float*)d_in[6];
    const float* a2b    = (const float*)d_in[7];
    const float* a3w    = (const float*)d_in[8];
    const float* a3b    = (const float*)d_in[9];
    const float* arw    = (const float*)d_in[10];
    const float* arb    = (const float*)d_in[11];
    const float* w02    = (const float*)d_in[12];
    const float* b02    = (const float*)d_in[13];
    const float* dwp    = (const float*)d_in[14];
    const float* dbp    = (const float*)d_in[15];
    float* out = (float*)d_out;

    static int s_inited = 0;
    if (!s_inited) {
        cudaFuncSetAttribute(k_conv1_mma,  cudaFuncAttributeMaxDynamicSharedMemorySize, C1_SMEM);
        cudaFuncSetAttribute(k_aspp_mma,   cudaFuncAttributeMaxDynamicSharedMemorySize, ASPP_SMEM);
        cudaFuncSetAttribute(k_fuse_mma,   cudaFuncAttributeMaxDynamicSharedMemorySize, FUSE_SMEM);
        cudaFuncSetAttribute(k_deform_mma, cudaFuncAttributeMaxDynamicSharedMemorySize, DEF_SMEM);
        s_inited = 1;
    }

    k_prep<<<1317, 256>>>(w01, a1w, a2w, a3w, arw, w02, dwp);
    k_conv1_mma<<<800, 256, C1_SMEM>>>(in_aux, in_ref, b01);

    dim3 ga(10, 20, 12);
    k_aspp_mma<<<ga, 256, ASPP_SMEM>>>(a1b, a2b, a3b);

    k_fuse_mma<<<800, 256, FUSE_SMEM>>>(arb, b02);
    k_deform_mma<<<800, 256, DEF_SMEM>>>(dbp, out);
}

// round 17
// speedup vs baseline: 1.0869x; 1.0869x over previous
#include <cuda_runtime.h>
#include <cuda_bf16.h>
#include <math.h>
#include <stdint.h>

#define HH 160
#define WW 160
#define HWW (160*160)
#define BB 4

typedef unsigned long long u64;

// ======================= PTX helpers (base ISA only) ========================
__device__ __forceinline__ uint32_t smem_u32(const void* p){
    uint32_t a; asm("{ .reg .u64 t; cvta.to.shared.u64 t, %1; cvt.u32.u64 %0, t; }" : "=r"(a) : "l"(p));
    return a;
}
__device__ __forceinline__ void cp16(uint32_t dst, const void* src){
    asm volatile("cp.async.ca.shared.global [%0], [%1], 16;" :: "r"(dst), "l"(src) : "memory");
}
__device__ __forceinline__ void cp16z(uint32_t dst, const void* src, int sz){
    asm volatile("cp.async.ca.shared.global [%0], [%1], 16, %2;" :: "r"(dst), "l"(src), "r"(sz) : "memory");
}
#define CP_COMMIT() asm volatile("cp.async.commit_group;" ::: "memory")

__device__ __forceinline__ void ldsm4(uint32_t* r, uint32_t a){
    asm volatile("ldmatrix.sync.aligned.m8n8.x4.shared.b16 {%0,%1,%2,%3}, [%4];"
      : "=r"(r[0]),"=r"(r[1]),"=r"(r[2]),"=r"(r[3]) : "r"(a));
}
__device__ __forceinline__ void mma_bf16(float* d, const uint32_t* a, const uint32_t* b){
    asm volatile("mma.sync.aligned.m16n8k16.row.col.f32.bf16.bf16.f32 "
      "{%0,%1,%2,%3}, {%4,%5,%6,%7}, {%8,%9}, {%0,%1,%2,%3};"
      : "+f"(d[0]),"+f"(d[1]),"+f"(d[2]),"+f"(d[3])
      : "r"(a[0]),"r"(a[1]),"r"(a[2]),"r"(a[3]),"r"(b[0]),"r"(b[1]));
}
__device__ __forceinline__ uint32_t swz(uint32_t r){ return r ^ ((r>>3)&0x70); }

// ================= device-global scratch (no allocation allowed) ============
__device__ __align__(16) float g_off1[BB*64*HWW];        // conv1 out NCHW (residual)
__device__ __align__(16) float g_off[BB*18*HWW];         // offsets NCHW
__device__ __align__(16) float g_xt [BB*HWW*64];         // in_aux NHWC fp32 (deform)
__device__ __align__(16) __nv_bfloat16 g_xh[BB*HWW*64];  // conv1 out NHWC bf16 hi
__device__ __align__(16) __nv_bfloat16 g_xl[BB*HWW*64];  // conv1 out NHWC bf16 lo
__device__ __align__(16) __nv_bfloat16 g_rh[(size_t)BB*HWW*192]; // concat NHWC hi
__device__ __align__(16) __nv_bfloat16 g_rl[(size_t)BB*HWW*192]; // concat NHWC lo
__device__ __align__(16) __nv_bfloat16 g_wb  [2*3*9*64*64]; // ASPP W [split][br][tap][co][ci]
__device__ __align__(16) __nv_bfloat16 g_arwb[2*3*64*64];   // fuse W [split][sub][co][ci]
__device__ __align__(16) __nv_bfloat16 g_dwb [2*9*64*64];   // deform W [split][tap][co][ci]
__device__ __align__(16) __nv_bfloat16 g_w01b[2*2*64*64];   // conv1 W [split][half][co][ci]
__device__ float g_w02t[64*18];

// ---------------------------------------------------------------------------
// prep: weight transposes + bf16 splits
// ---------------------------------------------------------------------------
__global__ void k_prep(const float* __restrict__ w01, const float* __restrict__ a1w,
                       const float* __restrict__ a2w, const float* __restrict__ a3w,
                       const float* __restrict__ arw, const float* __restrict__ w02,
                       const float* __restrict__ dw)
{
    int i = blockIdx.x*256 + threadIdx.x;
    if (i < 1152) { int c = i/18, j = i - c*18; g_w02t[i] = w02[j*64 + c]; return; }
    i -= 1152;
    if (i < 221184) {
        int s  = i / 110592;
        int q  = i % 110592;
        int br = q / 36864;
        int q2 = q % 36864;
        int tap = q2 / 4096;
        int r   = q2 % 4096;
        int co = r >> 6, ci = r & 63;
        const float* w = (br==0)?a1w:(br==1)?a2w:a3w;
        float v = w[(co*64+ci)*9 + tap];
        __nv_bfloat16 h = __float2bfloat16(v);
        g_wb[i] = (s==0) ? h : __float2bfloat16(v - __bfloat162float(h));
        return;
    }
    i -= 221184;
    if (i < 24576) {
        int s = i / 12288, q = i % 12288;
        int sub = q / 4096, r = q % 4096;
        int co = r >> 6, ci = r & 63;
        float v = arw[co*192 + sub*64 + ci];
        __nv_bfloat16 h = __float2bfloat16(v);
        g_arwb[i] = (s==0) ? h : __float2bfloat16(v - __bfloat162float(h));
        return;
    }
    i -= 24576;
    if (i < 73728) {
        int s = i / 36864, q = i % 36864;
        int tap = q / 4096, r = q % 4096;
        int co = r >> 6, ci = r & 63;
        float v = dw[(co*64+ci)*9 + tap];
        __nv_bfloat16 h = __float2bfloat16(v);
        g_dwb[i] = (s==0) ? h : __float2bfloat16(v - __bfloat162float(h));
        return;
    }
    i -= 73728;
    if (i < 16384) {
        int s = i / 8192, q = i % 8192;
        int half = q / 4096, r = q % 4096;
        int co = r >> 6, ci = r & 63;
        float v = w01[co*128 + half*64 + ci];
        __nv_bfloat16 h = __float2bfloat16(v);
        g_w01b[i] = (s==0) ? h : __float2bfloat16(v - __bfloat162float(h));
    }
}

// ---------------------------------------------------------------------------
// Kernel 1: conv1 1x1 128->64 + LReLU via mma, loading NCHW fp32 directly.
// half=0 staging pass ALSO writes g_xt (in_aux NHWC fp32).
// ---------------------------------------------------------------------------
#define C1_SMEM 100352

__global__ __launch_bounds__(256,2) void k_conv1_mma(
    const float* __restrict__ aux, const float* __restrict__ refi,
    const float* __restrict__ b01)
{
    extern __shared__ char smem[];
    uint32_t sb = smem_u32(smem);
    float* ts = (float*)(smem + 65536);     // [64][133] fp32 staging
    int tid = threadIdx.x, lane = tid&31, wid = tid>>5;
    int pxb = blockIdx.x*128;
    int b = pxb/HWW, hw0 = pxb%HWW;

    #pragma unroll
    for (int half = 0; half < 2; half++) {
        const float* src = (half ? refi : aux) + (size_t)b*64*HWW + hw0;
        if (half) __syncthreads();
        for (int i = tid; i < 2048; i += 256) {
            int ci = i>>5, g = i&31;
            float4 v = *(const float4*)(src + (size_t)ci*HWW + g*4);
            float* tp = &ts[ci*133 + g*4];
            tp[0]=v.x; tp[1]=v.y; tp[2]=v.z; tp[3]=v.w;
        }
        __syncthreads();
        for (int c = tid; c < 1024; c += 256) {
            int p = c>>3, ci8 = c&7;
            uint32_t hp[4], lp[4];
            #pragma unroll
            for (int k2 = 0; k2 < 4; k2++) {
                float v0 = ts[(ci8*8 + 2*k2  )*133 + p];
                float v1 = ts[(ci8*8 + 2*k2+1)*133 + p];
                __nv_bfloat16 h0 = __float2bfloat16(v0);
                __nv_bfloat16 h1 = __float2bfloat16(v1);
                hp[k2] = ((uint32_t)__bfloat16_as_ushort(h1)<<16) | __bfloat16_as_ushort(h0);
                __nv_bfloat162 l2 = __floats2bfloat162_rn(v0 - __bfloat162float(h0),
                                                          v1 - __bfloat162float(h1));
                lp[k2] = *(uint32_t*)&l2;
            }
            uint32_t rel = swz((uint32_t)(p*128 + ci8*16));
            *(uint4*)(smem + (half*2+0)*16384 + rel) = make_uint4(hp[0],hp[1],hp[2],hp[3]);
            *(uint4*)(smem + (half*2+1)*16384 + rel) = make_uint4(lp[0],lp[1],lp[2],lp[3]);
        }
        if (half == 0) {
            float* op = g_xt + ((size_t)b*HWW + hw0)*64;
            for (int i = tid; i < 8192; i += 256) {
                int p = i>>6, c = i&63;
                op[p*64 + c] = ts[c*133 + p];
            }
        }
    }
    __syncthreads();

    for (int c = tid; c < 2048; c += 256) {
        int t = c>>9, r = c&511;
        int half = t>>1, split = t&1;
        int co = r>>3, ci8 = r&7;
        const __nv_bfloat16* src = g_w01b + ((size_t)(split*2+half)*4096 + co*64 + ci8*8);
        cp16(sb + 65536 + t*8192 + swz((uint32_t)(co*128 + ci8*16)), src);
    }
    CP_COMMIT();
    asm volatile("cp.async.wait_group 0;" ::: "memory");
    __syncthreads();

    int m0 = (wid>>1)*32, n0 = (wid&1)*32;
    float d[2][4][4];
    #pragma unroll
    for (int mt = 0; mt < 2; mt++)
        #pragma unroll
        for (int nt = 0; nt < 4; nt++)
            #pragma unroll
            for (int e = 0; e < 4; e++) d[mt][nt][e] = 0.f;

    #pragma unroll
    for (int half = 0; half < 2; half++) {
        uint32_t Ah = sb + (half*2+0)*16384;
        uint32_t Al = sb + (half*2+1)*16384;
        uint32_t Bh = sb + 65536 + (uint32_t)((half*2+0)*8192);
        uint32_t Bl = sb + 65536 + (uint32_t)((half*2+1)*8192);
        #pragma unroll
        for (int ks = 0; ks < 4; ks++) {
            uint32_t ah[2][4], al[2][4], bh[4][2], bl[4][2];
            #pragma unroll
            for (int mt = 0; mt < 2; mt++) {
                uint32_t rel = (uint32_t)((m0 + mt*16 + (lane&15))*128
                                          + ks*32 + (lane>>4)*16);
                ldsm4(ah[mt], Ah + swz(rel));
                ldsm4(al[mt], Al + swz(rel));
            }
            #pragma unroll
            for (int nt2 = 0; nt2 < 2; nt2++) {
                int mid = lane>>3;
                int row = n0 + nt2*16 + (mid>>1)*8 + (lane&7);
                uint32_t rel = (uint32_t)(row*128 + ks*32 + (mid&1)*16);
                uint32_t r4[4];
                ldsm4(r4, Bh + swz(rel));
                bh[nt2*2][0]=r4[0]; bh[nt2*2][1]=r4[1];
                bh[nt2*2+1][0]=r4[2]; bh[nt2*2+1][1]=r4[3];
                ldsm4(r4, Bl + swz(rel));
                bl[nt2*2][0]=r4[0]; bl[nt2*2][1]=r4[1];
                bl[nt2*2+1][0]=r4[2]; bl[nt2*2+1][1]=r4[3];
            }
            #pragma unroll
            for (int mt = 0; mt < 2; mt++)
                #pragma unroll
                for (int nt = 0; nt < 4; nt++) {
                    mma_bf16(d[mt][nt], ah[mt], bh[nt]);
                    mma_bf16(d[mt][nt], ah[mt], bl[nt]);
                    mma_bf16(d[mt][nt], al[mt], bh[nt]);
                }
        }
    }

    float* ep = (float*)smem;
    __syncthreads();
    #pragma unroll
    for (int mt = 0; mt < 2; mt++)
        #pragma unroll
        for (int nt = 0; nt < 4; nt++) {
            int px = m0 + mt*16 + (lane>>2);
            int co = n0 + nt*8 + (lane&3)*2;
            ep[px*66 + co]       = d[mt][nt][0];
            ep[px*66 + co + 1]   = d[mt][nt][1];
            ep[(px+8)*66 + co]   = d[mt][nt][2];
            ep[(px+8)*66 + co+1] = d[mt][nt][3];
        }
    __syncthreads();
    float* op = g_off1 + (size_t)b*64*HWW + hw0;
    for (int i = tid; i < 8192; i += 256) {
        int co = i>>7, p = i&127;
        float v = ep[p*66 + co] + __ldg(&b01[co]);
        v = (v >= 0.f) ? v : 0.1f*v;
        op[(size_t)co*HWW + p] = v;
    }
    for (int i = tid; i < 8192; i += 256) {
        int p = i>>6, co = i&63;
        float v = ep[p*66 + co] + __ldg(&b01[co]);
        v = (v >= 0.f) ? v : 0.1f*v;
        size_t gp = (size_t)b*HWW + hw0 + p;
        __nv_bfloat16 h = __float2bfloat16(v);
        g_xh[gp*64 + co] = h;
        g_xl[gp*64 + co] = __float2bfloat16(v - __bfloat162float(h));
    }
}

// ---------------------------------------------------------------------------
// Kernel 2: ASPP dilated 3x3 via mma.sync bf16-split (96KB, 2 CTAs/SM)
// ---------------------------------------------------------------------------
#define ASPP_SMEM 98304

__global__ __launch_bounds__(256,2) void k_aspp_mma(
    const float* __restrict__ b1, const float* __restrict__ b2,
    const float* __restrict__ b3)
{
    extern __shared__ char smem[];
    uint32_t sb = smem_u32(smem);
    int tid = threadIdx.x, lane = tid&31, wid = tid>>5;
    int z = blockIdx.z, b = z&3, br = z>>2;
    int D = 1<<br;
    const float* bias = (br==0)?b1:((br==1)?b2:b3);
    int x0 = blockIdx.x*16, y0 = blockIdx.y*8;

    auto issueT = [&](int t, int stage){
        int ky = t/3, kx = t - ky*3;
        int dy = (ky-1)*D, dx = (kx-1)*D;
        #pragma unroll
        for (int j = 0; j < 8; j++) {
            int c = tid + j*256;
            int split = c>>10, rem = c&1023, p = rem>>3, ci8 = rem&7;
            int gy = y0 + (p>>4) + dy, gx = x0 + (p&15) + dx;
            bool ok = (gy>=0)&&(gy<HH)&&(gx>=0)&&(gx<WW);
            const __nv_bfloat16* base = split ? g_xl : g_xh;
            const __nv_bfloat16* src =
                base + (((size_t)b*HWW + (ok ? gy*WW+gx : 0))*64 + ci8*8);
            uint32_t rel = (uint32_t)(p*128 + ci8*16);
            cp16z(sb + (stage*2+split)*16384 + swz(rel), src, ok?16:0);
        }
        #pragma unroll
        for (int j = 0; j < 4; j++) {
            int c = tid + j*256;
            int split = c>>9, r = c&511;
            int co = r>>3, ci8 = r&7;
            const __nv_bfloat16* src =
                g_wb + (((size_t)(split*3+br)*9 + t)*4096 + co*64 + ci8*8);
            cp16(sb + 65536 + (stage*2+split)*8192 + swz((uint32_t)(co*128 + ci8*16)), src);
        }
        CP_COMMIT();
    };
    issueT(0, 0);
    issueT(1, 1);

    int m0 = (wid>>1)*32, n0 = (wid&1)*32;
    float d[2][4][4];
    #pragma unroll
    for (int mt = 0; mt < 2; mt++)
        #pragma unroll
        for (int nt = 0; nt < 4; nt++)
            #pragma unroll
            for (int e = 0; e < 4; e++) d[mt][nt][e] = 0.f;

    #pragma unroll 1
    for (int t = 0; t < 9; t++) {
        if (t < 8) asm volatile("cp.async.wait_group 1;" ::: "memory");
        else       asm volatile("cp.async.wait_group 0;" ::: "memory");
        __syncthreads();
        int stage = t & 1;
        uint32_t Ah = sb + (stage*2+0)*16384;
        uint32_t Al = sb + (stage*2+1)*16384;
        uint32_t Bh = sb + 65536 + (uint32_t)((stage*2+0)*8192);
        uint32_t Bl = sb + 65536 + (uint32_t)((stage*2+1)*8192);
        #pragma unroll
        for (int ks = 0; ks < 4; ks++) {
            uint32_t ah[2][4], al[2][4], bh[4][2], bl[4][2];
            #pragma unroll
            for (int mt = 0; mt < 2; mt++) {
                uint32_t rel = (uint32_t)((m0 + mt*16 + (lane&15))*128
                                          + ks*32 + (lane>>4)*16);
                ldsm4(ah[mt], Ah + swz(rel));
                ldsm4(al[mt], Al + swz(rel));
            }
            #pragma unroll
            for (int nt2 = 0; nt2 < 2; nt2++) {
                int mid = lane>>3;
                int row = n0 + nt2*16 + (mid>>1)*8 + (lane&7);
                uint32_t rel = (uint32_t)(row*128 + ks*32 + (mid&1)*16);
                uint32_t r4[4];
                ldsm4(r4, Bh + swz(rel));
                bh[nt2*2][0]=r4[0]; bh[nt2*2][1]=r4[1];
                bh[nt2*2+1][0]=r4[2]; bh[nt2*2+1][1]=r4[3];
                ldsm4(r4, Bl + swz(rel));
                bl[nt2*2][0]=r4[0]; bl[nt2*2][1]=r4[1];
                bl[nt2*2+1][0]=r4[2]; bl[nt2*2+1][1]=r4[3];
            }
            #pragma unroll
            for (int mt = 0; mt < 2; mt++)
                #pragma unroll
                for (int nt = 0; nt < 4; nt++) {
                    mma_bf16(d[mt][nt], ah[mt], bh[nt]);
                    mma_bf16(d[mt][nt], ah[mt], bl[nt]);
                    mma_bf16(d[mt][nt], al[mt], bh[nt]);
                }
        }
        __syncthreads();
        if (t < 7) issueT(t+2, stage);
    }

    float* ep = (float*)smem;
    #pragma unroll
    for (int mt = 0; mt < 2; mt++)
        #pragma unroll
        for (int nt = 0; nt < 4; nt++) {
            int px = m0 + mt*16 + (lane>>2);
            int co = n0 + nt*8 + (lane&3)*2;
            ep[px*66 + co]       = d[mt][nt][0];
            ep[px*66 + co + 1]   = d[mt][nt][1];
            ep[(px+8)*66 + co]   = d[mt][nt][2];
            ep[(px+8)*66 + co+1] = d[mt][nt][3];
        }
    __syncthreads();
    for (int i = tid; i < 8192; i += 256) {
        int p = i>>6, co = i&63;
        float v = ep[p*66 + co] + __ldg(&bias[co]);
        v = (v >= 0.f) ? v : 0.1f*v;
        size_t gp = (size_t)b*HWW + (size_t)(y0 + (p>>4))*WW + x0 + (p&15);
        __nv_bfloat16 h = __float2bfloat16(v);
        g_rh[gp*192 + br*64 + co] = h;
        g_rl[gp*192 + br*64 + co] = __float2bfloat16(v - __bfloat162float(h));
    }
}

// ---------------------------------------------------------------------------
// Kernel 3: fuse 1x1 192->64 + bias + residual + fused offset head (64->18).
// Head epilogue parallel: thread=(px, jg), 9 accumulators, warp-uniform w2.
// ---------------------------------------------------------------------------
#define FUSE_SMEM 114688

__global__ __launch_bounds__(256,2) void k_fuse_mma(const float* __restrict__ arb,
                                                    const float* __restrict__ b02)
{
    extern __shared__ char smem[];
    uint32_t sb = smem_u32(smem);
    int tid = threadIdx.x, lane = tid&31, wid = tid>>5;
    int pxb = blockIdx.x*128;
    int b = pxb/HWW, hw0 = pxb%HWW;

    auto issueA = [&](int sub, int stage){
        #pragma unroll
        for (int j = 0; j < 8; j++) {
            int c = tid + j*256;
            int split = c>>10, r = c&1023;
            int p = r>>3, ci8 = r&7;
            const __nv_bfloat16* base = split ? g_rl : g_rh;
            const __nv_bfloat16* src = base + ((size_t)(b*HWW + hw0 + p)*192 + sub*64 + ci8*8);
            cp16(sb + (stage*2+split)*16384 + swz((uint32_t)(p*128 + ci8*16)), src);
        }
        CP_COMMIT();
    };
    for (int c = tid; c < 3072; c += 256) {
        int t = c>>9, r = c&511;
        int sub = t>>1, split = t&1;
        int co = r>>3, ci8 = r&7;
        const __nv_bfloat16* src = g_arwb + ((size_t)(split*3+sub)*4096 + co*64 + ci8*8);
        cp16(sb + 65536 + t*8192 + swz((uint32_t)(co*128 + ci8*16)), src);
    }
    issueA(0, 0);
    issueA(1, 1);

    int m0 = (wid>>1)*32, n0 = (wid&1)*32;
    float d[2][4][4];
    #pragma unroll
    for (int mt = 0; mt < 2; mt++)
        #pragma unroll
        for (int nt = 0; nt < 4; nt++)
            #pragma unroll
            for (int e = 0; e < 4; e++) d[mt][nt][e] = 0.f;

    #pragma unroll 1
    for (int sub = 0; sub < 3; sub++) {
        if (sub < 2) asm volatile("cp.async.wait_group 1;" ::: "memory");
        else         asm volatile("cp.async.wait_group 0;" ::: "memory");
        __syncthreads();
        int stage = sub & 1;
        uint32_t Ah = sb + (stage*2+0)*16384;
        uint32_t Al = sb + (stage*2+1)*16384;
        uint32_t Bh = sb + 65536 + (uint32_t)((sub*2+0)*8192);
        uint32_t Bl = sb + 65536 + (uint32_t)((sub*2+1)*8192);
        #pragma unroll
        for (int ks = 0; ks < 4; ks++) {
            uint32_t ah[2][4], al[2][4], bh[4][2], bl[4][2];
            #pragma unroll
            for (int mt = 0; mt < 2; mt++) {
                uint32_t rel = (uint32_t)((m0 + mt*16 + (lane&15))*128
                                          + ks*32 + (lane>>4)*16);
                ldsm4(ah[mt], Ah + swz(rel));
                ldsm4(al[mt], Al + swz(rel));
            }
            #pragma unroll
            for (int nt2 = 0; nt2 < 2; nt2++) {
                int mid = lane>>3;
                int row = n0 + nt2*16 + (mid>>1)*8 + (lane&7);
                uint32_t rel = (uint32_t)(row*128 + ks*32 + (mid&1)*16);
                uint32_t r4[4];
                ldsm4(r4, Bh + swz(rel));
                bh[nt2*2][0]=r4[0]; bh[nt2*2][1]=r4[1];
                bh[nt2*2+1][0]=r4[2]; bh[nt2*2+1][1]=r4[3];
                ldsm4(r4, Bl + swz(rel));
                bl[nt2*2][0]=r4[0]; bl[nt2*2][1]=r4[1];
                bl[nt2*2+1][0]=r4[2]; bl[nt2*2+1][1]=r4[3];
            }
            #pragma unroll
            for (int mt = 0; mt < 2; mt++)
                #pragma unroll
                for (int nt = 0; nt < 4; nt++) {
                    mma_bf16(d[mt][nt], ah[mt], bh[nt]);
                    mma_bf16(d[mt][nt], ah[mt], bl[nt]);
                    mma_bf16(d[mt][nt], al[mt], bh[nt]);
                }
        }
        __syncthreads();
        if (sub < 1) issueA(sub+2, stage);
    }

    float* ep = (float*)smem;              // [128][66]
    float* w2 = (float*)(smem + 36864);    // [64][18]
    #pragma unroll
    for (int mt = 0; mt < 2; mt++)
        #pragma unroll
        for (int nt = 0; nt < 4; nt++) {
            int px = m0 + mt*16 + (lane>>2);
            int co = n0 + nt*8 + (lane&3)*2;
            ep[px*66 + co]       = d[mt][nt][0];
            ep[px*66 + co + 1]   = d[mt][nt][1];
            ep[(px+8)*66 + co]   = d[mt][nt][2];
            ep[(px+8)*66 + co+1] = d[mt][nt][3];
        }
    for (int i = tid; i < 1152; i += 256) w2[i] = g_w02t[i];
    __syncthreads();

    const float* xb = g_off1 + (size_t)b*64*HWW + hw0;
    for (int i = tid; i < 8192; i += 256) {
        int co = i>>7, p = i&127;
        ep[p*66 + co] += __ldg(&arb[co]) + xb[(size_t)co*HWW + p];
    }
    __syncthreads();

    {
        int px = tid & 127, jg = tid >> 7;
        float acc[9];
        #pragma unroll
        for (int t = 0; t < 9; t++) acc[t] = __ldg(&b02[jg*9 + t]);
        const float* er = &ep[px*66];
        for (int co = 0; co < 64; co++) {
            float e = er[co];
            const float* wr = &w2[co*18 + jg*9];
            #pragma unroll
            for (int t = 0; t < 9; t++) acc[t] += e * wr[t];
        }
        float* oo = g_off + (size_t)b*18*HWW + hw0 + px;
        #pragma unroll
        for (int t = 0; t < 9; t++) oo[(size_t)(jg*9 + t)*HWW] = acc[t];
    }
}

// ---------------------------------------------------------------------------
// Kernel 4: deformable conv via mma.sync bf16-split (2 CTAs/SM, R14 version)
// ---------------------------------------------------------------------------
#define DEF_SMEM 69632

__global__ __launch_bounds__(256,2) void k_deform_mma(const float* __restrict__ db,
                                                      float* __restrict__ out)
{
    extern __shared__ char smem[];
    uint32_t sb = smem_u32(smem);
    int tid = threadIdx.x, lane = tid&31, wid = tid>>5;
    int pxb = blockIdx.x*128;
    int b = pxb/HWW, hw0 = pxb%HWW;
    float* pw_s = (float*)(smem + 65536);
    int*   pi_s = (int*)(smem + 65536 + 2048);

    auto issueW = [&](int t){
        int s = t&1;
        #pragma unroll
        for (int j = 0; j < 4; j++) {
            int c = tid + j*256;
            int split = c>>9, r = c&511;
            int co = r>>3, ci8 = r&7;
            const __nv_bfloat16* src = g_dwb + ((size_t)(split*9 + t)*4096 + co*64 + ci8*8);
            cp16(sb + 32768 + s*16384 + split*8192 + swz((uint32_t)(co*128 + ci8*16)), src);
        }
        CP_COMMIT();
    };
    issueW(0);

    int m0 = (wid>>1)*32, n0 = (wid&1)*32;
    float d[2][4][4];
    #pragma unroll
    for (int mt = 0; mt < 2; mt++)
        #pragma unroll
        for (int nt = 0; nt < 4; nt++)
            #pragma unroll
            for (int e = 0; e < 4; e++) d[mt][nt][e] = 0.f;

    const float* xb = g_xt + (size_t)b*HWW*64;

    #pragma unroll 1
    for (int k = 0; k < 9; k++) {
        if (tid < 128) {
            int px = tid, hw = hw0 + px;
            int h = hw/WW, w = hw - h*WW;
            int ky = k/3, kx = k - ky*3;
            const float* offb = g_off + (size_t)b*18*HWW + hw;
            float py  = (float)(h - 1 + ky) + offb[(size_t)(2*k)*HWW];
            float pxf = (float)(w - 1 + kx) + offb[(size_t)(2*k+1)*HWW];
            float fy = floorf(py), fx = floorf(pxf);
            int iy = (int)fy, ix = (int)fx;
            float wy = py - fy, wx = pxf - fx;
            bool vy0 = (iy   >= 0 && iy   < HH);
            bool vy1 = (iy+1 >= 0 && iy+1 < HH);
            bool vx0 = (ix   >= 0 && ix   < WW);
            bool vx1 = (ix+1 >= 0 && ix+1 < WW);
            float w00 = (1.f-wy)*(1.f-wx); if (!(vy0&&vx0)) w00 = 0.f;
            float w01 = (1.f-wy)*wx;       if (!(vy0&&vx1)) w01 = 0.f;
            float w10 = wy*(1.f-wx);       if (!(vy1&&vx0)) w10 = 0.f;
            float w11 = wy*wx;             if (!(vy1&&vx1)) w11 = 0.f;
            int cy0 = min(max(iy,0),HH-1),   cy1 = min(max(iy+1,0),HH-1);
            int cx0 = min(max(ix,0),WW-1),   cx1 = min(max(ix+1,0),WW-1);
            pw_s[px*4+0] = w00; pw_s[px*4+1] = w01;
            pw_s[px*4+2] = w10; pw_s[px*4+3] = w11;
            pi_s[px*4+0] = (cy0*WW + cx0)*64; pi_s[px*4+1] = (cy0*WW + cx1)*64;
            pi_s[px*4+2] = (cy1*WW + cx0)*64; pi_s[px*4+3] = (cy1*WW + cx1)*64;
        }
        if (k < 8) issueW(k+1);
        __syncthreads();

        {
            int px = tid>>1, ch0 = (tid&1)*32;
            float w00 = pw_s[px*4+0], w01v = pw_s[px*4+1];
            float w10 = pw_s[px*4+2], w11  = pw_s[px*4+3];
            int i00 = pi_s[px*4+0], i01 = pi_s[px*4+1];
            int i10 = pi_s[px*4+2], i11 = pi_s[px*4+3];
            #pragma unroll
            for (int q = 0; q < 8; q++) {
                int c = ch0 + q*4;
                float4 A = *(const float4*)(xb + i00 + c);
                float4 Bq= *(const float4*)(xb + i01 + c);
                float4 C = *(const float4*)(xb + i10 + c);
                float4 Dq= *(const float4*)(xb + i11 + c);
                float s0 = w00*A.x + w01v*Bq.x + w10*C.x + w11*Dq.x;
                float s1 = w00*A.y + w01v*Bq.y + w10*C.y + w11*Dq.y;
                float s2 = w00*A.z + w01v*Bq.z + w10*C.z + w11*Dq.z;
                float s3 = w00*A.w + w01v*Bq.w + w10*C.w + w11*Dq.w;
                __nv_bfloat16 h0 = __float2bfloat16(s0);
                __nv_bfloat16 h1 = __float2bfloat16(s1);
                __nv_bfloat16 h2 = __float2bfloat16(s2);
                __nv_bfloat16 h3 = __float2bfloat16(s3);
                uint32_t hp0 = (uint32_t)__bfloat16_as_ushort(h1)<<16 | __bfloat16_as_ushort(h0);
                uint32_t hp1 = (uint32_t)__bfloat16_as_ushort(h3)<<16 | __bfloat16_as_ushort(h2);
                __nv_bfloat162 lp0 = __floats2bfloat162_rn(s0 - __bfloat162float(h0),
                                                           s1 - __bfloat162float(h1));
                __nv_bfloat162 lp1 = __floats2bfloat162_rn(s2 - __bfloat162float(h2),
                                                           s3 - __bfloat162float(h3));
                uint32_t rel = (uint32_t)(px*128 + c*2);
                *(uint32_t*)(smem + swz(rel))          = hp0;
                *(uint32_t*)(smem + swz(rel+4))        = hp1;
                *(uint32_t*)(smem + 16384 + swz(rel))  = *(uint32_t*)&lp0;
                *(uint32_t*)(smem + 16384 + swz(rel+4))= *(uint32_t*)&lp1;
            }
        }
        if (k < 8) asm volatile("cp.async.wait_group 1;" ::: "memory");
        else       asm volatile("cp.async.wait_group 0;" ::: "memory");
        __syncthreads();

        uint32_t Ah = sb, Al = sb + 16384;
        uint32_t Bh = sb + 32768 + (uint32_t)((k&1)*16384);
        uint32_t Bl = Bh + 8192;
        #pragma unroll
        for (int ks = 0; ks < 4; ks++) {
            uint32_t ah[2][4], al[2][4], bh[4][2], bl[4][2];
            #pragma unroll
            for (int mt = 0; mt < 2; mt++) {
                uint32_t rel = (uint32_t)((m0 + mt*16 + (lane&15))*128
                                          + ks*32 + (lane>>4)*16);
                ldsm4(ah[mt], Ah + swz(rel));
                ldsm4(al[mt], Al + swz(rel));
            }
            #pragma unroll
            for (int nt2 = 0; nt2 < 2; nt2++) {
                int mid = lane>>3;
                int row = n0 + nt2*16 + (mid>>1)*8 + (lane&7);
                uint32_t rel = (uint32_t)(row*128 + ks*32 + (mid&1)*16);
                uint32_t r4[4];
                ldsm4(r4, Bh + swz(rel));
                bh[nt2*2][0]=r4[0]; bh[nt2*2][1]=r4[1];
                bh[nt2*2+1][0]=r4[2]; bh[nt2*2+1][1]=r4[3];
                ldsm4(r4, Bl + swz(rel));
                bl[nt2*2][0]=r4[0]; bl[nt2*2][1]=r4[1];
                bl[nt2*2+1][0]=r4[2]; bl[nt2*2+1][1]=r4[3];
            }
            #pragma unroll
            for (int mt = 0; mt < 2; mt++)
                #pragma unroll
                for (int nt = 0; nt < 4; nt++) {
                    mma_bf16(d[mt][nt], ah[mt], bh[nt]);
                    mma_bf16(d[mt][nt], ah[mt], bl[nt]);
                    mma_bf16(d[mt][nt], al[mt], bh[nt]);
                }
        }
        __syncthreads();
    }

    float* ep = (float*)smem;
    #pragma unroll
    for (int mt = 0; mt < 2; mt++)
        #pragma unroll
        for (int nt = 0; nt < 4; nt++) {
            int px = m0 + mt*16 + (lane>>2);
            int co = n0 + nt*8 + (lane&3)*2;
            ep[px*66 + co]       = d[mt][nt][0];
            ep[px*66 + co + 1]   = d[mt][nt][1];
            ep[(px+8)*66 + co]   = d[mt][nt][2];
            ep[(px+8)*66 + co+1] = d[mt][nt][3];
        }
    __syncthreads();
    float* op = out + (size_t)b*64*HWW + hw0;
    for (int i = tid; i < 8192; i += 256) {
        int co = i>>7, p = i&127;
        op[(size_t)co*HWW + p] = ep[p*66 + co] + __ldg(&db[co]);
    }
}

// ===========================================================================
extern "C" void kernel_launch(void* const* d_in, const int* in_sizes, int n_in,
                              void* d_out, int out_size)
{
    const float* in_aux = (const float*)d_in[0];
    const float* in_ref = (const float*)d_in[1];
    const float* w01    = (const float*)d_in[2];
    const float* b01    = (const float*)d_in[3];
    const float* a1w    = (const float*)d_in[4];
    const float* a1b    = (const float*)d_in[5];
    const float* a2w    = (const float*)d_in[6];
    const float* a2b    = (const float*)d_in[7];
    const float* a3w    = (const float*)d_in[8];
    const float* a3b    = (const float*)d_in[9];
    const float* arw    = (const float*)d_in[10];
    const float* arb    = (const float*)d_in[11];
    const float* w02    = (const float*)d_in[12];
    const float* b02    = (const float*)d_in[13];
    const float* dwp    = (const float*)d_in[14];
    const float* dbp    = (const float*)d_in[15];
    float* out = (float*)d_out;

    static int s_inited = 0;
    if (!s_inited) {
        cudaFuncSetAttribute(k_conv1_mma,  cudaFuncAttributeMaxDynamicSharedMemorySize, C1_SMEM);
        cudaFuncSetAttribute(k_aspp_mma,   cudaFuncAttributeMaxDynamicSharedMemorySize, ASPP_SMEM);
        cudaFuncSetAttribute(k_fuse_mma,   cudaFuncAttributeMaxDynamicSharedMemorySize, FUSE_SMEM);
        cudaFuncSetAttribute(k_deform_mma, cudaFuncAttributeMaxDynamicSharedMemorySize, DEF_SMEM);
        s_inited = 1;
    }

    k_prep<<<1317, 256>>>(w01, a1w, a2w, a3w, arw, w02, dwp);
    k_conv1_mma<<<800, 256, C1_SMEM>>>(in_aux, in_ref, b01);

    dim3 ga(10, 20, 12);
    k_aspp_mma<<<ga, 256, ASPP_SMEM>>>(a1b, a2b, a3b);

    k_fuse_mma<<<800, 256, FUSE_SMEM>>>(arb, b02);
    k_deform_mma<<<800, 256, DEF_SMEM>>>(dbp, out);
}